// round 4
// baseline (speedup 1.0000x reference)
#include <cuda_runtime.h>
#include <cstdint>

// LmulLinear: out[m,p] = sum_k bitcast_f32(bits(x[m,k]) + bits(w[p,k]) - OFFSET) + bias[p]
// M=256, K=512, P=512.
//
// R4: 8x2 microtile (b-reuse across 8 m-rows; a-loads are warp broadcasts),
//     fused pack+f32x2 add (no stray MOVs), split-K x8 over shared full-K tiles.

#define M_DIM 256
#define K_DIM 512
#define P_DIM 512
#define BM 32
#define BN 32
#define GROUPS 8
#define KG (K_DIM / GROUPS)      // 64 k per group
#define TPG 64                   // threads per group
#define SROW (K_DIM + 4)         // 516 words; mod 32 == 4 -> 2-phase (minimal) LDS.128
#define TILE_WORDS (BM * SROW)   // 16512
#define SMEM_BYTES (2 * TILE_WORDS * 4)  // 132096 B

// acc(f32x2) += ( f32(a+b0), f32(a+b1) ) ; lo/hi allocated as pair -> MOV elided
#define LMAC(acc, a, b0, b1)                                                   \
    asm("{\n\t"                                                                \
        ".reg .b32 lo, hi;\n\t"                                                \
        ".reg .b64 t;\n\t"                                                     \
        "add.u32 lo, %1, %2;\n\t"                                              \
        "add.u32 hi, %1, %3;\n\t"                                              \
        "mov.b64 t, {lo, hi};\n\t"                                             \
        "add.rn.f32x2 %0, %0, t;\n\t"                                          \
        "}" : "+l"(acc) : "r"(a), "r"(b0), "r"(b1))

extern __shared__ uint32_t smem[];

__global__ void __launch_bounds__(512, 1)
lmul_linear_kernel(const float* __restrict__ x,
                   const float* __restrict__ w,
                   const float* __restrict__ bias,
                   float* __restrict__ out)
{
    constexpr uint32_t OFFSET = 1064828928u;  // 0x3F780000

    const int tid = threadIdx.x;
    const int g   = tid >> 6;        // k-group 0..7
    const int lt  = tid & 63;        // lane in group
    const int tx  = lt & 15;         // p coord: cols tx, tx+16
    const int tyg = lt >> 4;         // 0..3 -> m rows tyg*8 .. +7
    const int m0  = blockIdx.y * BM;
    const int p0  = blockIdx.x * BN;

    uint32_t* As = smem;               // [BM][SROW], full K
    uint32_t* Bs = smem + TILE_WORDS;  // [BN][SROW], full K, offset-folded

    const uint32_t* __restrict__ xu = reinterpret_cast<const uint32_t*>(x);
    const uint32_t* __restrict__ wu = reinterpret_cast<const uint32_t*>(w);

    // ---- cooperative load of full-K tiles: 32 rows x 128 uint4 each ----
    #pragma unroll
    for (int i = 0; i < 8; i++) {
        int idx = tid + i * 512;         // 0..4095
        int row = idx >> 7;              // 128 uint4 per row
        int c   = (idx & 127) * 4;       // word col
        uint4 va = *reinterpret_cast<const uint4*>(&xu[(m0 + row) * K_DIM + c]);
        *reinterpret_cast<uint4*>(&As[row * SROW + c]) = va;
        uint4 vb = *reinterpret_cast<const uint4*>(&wu[(p0 + row) * K_DIM + c]);
        vb.x -= OFFSET; vb.y -= OFFSET; vb.z -= OFFSET; vb.w -= OFFSET;
        *reinterpret_cast<uint4*>(&Bs[row * SROW + c]) = vb;
    }
    __syncthreads();

    // ---- main loop over this group's 64-k slice ----
    const int kbase = g * KG;
    const uint32_t* ap = As + (tyg * 8) * SROW + kbase;  // 8 consecutive rows
    const uint32_t* b0p = Bs + tx * SROW + kbase;
    const uint32_t* b1p = Bs + (tx + 16) * SROW + kbase;

    uint64_t acc[8];
    #pragma unroll
    for (int r = 0; r < 8; r++) acc[r] = 0ull;

    #pragma unroll 4
    for (int j = 0; j < KG / 4; j++) {
        uint4 b0 = *reinterpret_cast<const uint4*>(b0p + 4 * j);
        uint4 b1 = *reinterpret_cast<const uint4*>(b1p + 4 * j);
        #pragma unroll
        for (int r = 0; r < 8; r++) {
            uint4 a = *reinterpret_cast<const uint4*>(ap + r * SROW + 4 * j);
            LMAC(acc[r], a.x, b0.x, b1.x);
            LMAC(acc[r], a.y, b0.y, b1.y);
            LMAC(acc[r], a.z, b0.z, b1.z);
            LMAC(acc[r], a.w, b0.w, b1.w);
        }
    }

    // ---- cross-group reduction: groups 1..7 publish, group 0 combines ----
    uint64_t* Red = reinterpret_cast<uint64_t*>(smem);  // 7*64*8 u64 = 28 KB, reuses As

    __syncthreads();   // tiles fully consumed
    if (g > 0) {
        uint64_t* rr = Red + ((g - 1) * TPG + lt) * 8;
        #pragma unroll
        for (int r = 0; r < 8; r++) rr[r] = acc[r];
    }
    __syncthreads();

    if (g == 0) {
        #pragma unroll
        for (int gg = 0; gg < 7; gg++) {
            const uint64_t* rr = Red + (gg * TPG + lt) * 8;
            #pragma unroll
            for (int r = 0; r < 8; r++) {
                uint64_t v = rr[r];
                asm("add.rn.f32x2 %0, %0, %1;" : "+l"(acc[r]) : "l"(v));
            }
        }

        const int p = p0 + tx;
        uint32_t blo = reinterpret_cast<const uint32_t*>(bias)[p];
        uint32_t bhi = reinterpret_cast<const uint32_t*>(bias)[p + 16];
        uint64_t bp;
        asm("mov.b64 %0, {%1, %2};" : "=l"(bp) : "r"(blo), "r"(bhi));

        const int mbase = m0 + tyg * 8;
        #pragma unroll
        for (int r = 0; r < 8; r++) {
            asm("add.rn.f32x2 %0, %0, %1;" : "+l"(acc[r]) : "l"(bp));
            uint32_t lo, hi;
            asm("mov.b64 {%0, %1}, %2;" : "=r"(lo), "=r"(hi) : "l"(acc[r]));
            uint32_t* orow = reinterpret_cast<uint32_t*>(out) + (mbase + r) * P_DIM;
            orow[p]      = lo;
            orow[p + 16] = hi;
        }
    }
}

extern "C" void kernel_launch(void* const* d_in, const int* in_sizes, int n_in,
                              void* d_out, int out_size)
{
    const float* x    = (const float*)d_in[0];   // (256, 512)
    const float* w    = (const float*)d_in[1];   // (512, 512)
    const float* bias = (const float*)d_in[2];   // (512,)
    float* out = (float*)d_out;                  // (256, 512)

    cudaFuncSetAttribute(lmul_linear_kernel,
                         cudaFuncAttributeMaxDynamicSharedMemorySize, SMEM_BYTES);

    dim3 grid(P_DIM / BN, M_DIM / BM);  // (16, 8) = 128 CTAs
    lmul_linear_kernel<<<grid, 512, SMEM_BYTES>>>(x, w, bias, out);
}